// round 7
// baseline (speedup 1.0000x reference)
#include <cuda_runtime.h>
#include <cuda_bf16.h>
#include <math.h>
#include <stdint.h>

#define Bx 4
#define Sx 128
#define Dx 256
#define Hx 8

static __device__ float  g_V [Bx*Sx*Dx];     // V = x@Wv.T + bv
static __device__ float  g_AO[Bx*Sx*Dx];     // attention output (pre-Wo)
static __device__ float  g_AB[Bx*Hx*Sx*6];   // per (b,h,i): A1,B1,A2,B2,A3,B3
static __device__ float4 g_CK[Bx*Hx*Sx];     // per (b,h,j): cos(k1..k3), pad

// ===========================================================================
// Legacy tensor-core mma (baseline sm_103 ISA, no 'a' feature needed):
// m16n8k16 row.col f32.bf16.bf16.f32
// ===========================================================================
__device__ __forceinline__ void mma16816(float* d, const uint32_t* a, const uint32_t* b)
{
    asm volatile(
        "mma.sync.aligned.m16n8k16.row.col.f32.bf16.bf16.f32 "
        "{%0,%1,%2,%3}, {%4,%5,%6,%7}, {%8,%9}, {%0,%1,%2,%3};\n"
        : "+f"(d[0]), "+f"(d[1]), "+f"(d[2]), "+f"(d[3])
        : "r"(a[0]), "r"(a[1]), "r"(a[2]), "r"(a[3]), "r"(b[0]), "r"(b[1]));
}

// ===========================================================================
// Tensor GEMM: C[m0+32][n0+64] = A @ B^T + bias, A[*,256], B[n,256] (NT).
// bf16 hi/lo split: D = Ah*Bh + Ah*Bl + Al*Bh  (err ~8e-6 rel).
// smem layout: uint32 [rows][36] (32 k-pairs + 4 pad) -> fragment LDS.32
// addr (l>>2)*36 + (l&3) hits bank (l>>2)*4 + (l&3): bijective, conflict-free.
// 256 thr = 8 warps = 2m x 4n of 16m x 16n warp tiles. K chunks of 64.
// ===========================================================================
#define AH_OFF 0            // [32][36] uint32
#define AL_OFF 1152
#define BH_OFF 2304         // [64][36]
#define BL_OFF 4608
#define SM_WORDS 6912       // 27.6KB

__device__ __forceinline__ void gemm_tc(
    const float4* __restrict__ A4, const float4* __restrict__ B4,
    const float* __restrict__ bias, float* __restrict__ C,
    int m0, int n0, uint32_t* sm)
{
    uint32_t* AsH = sm + AH_OFF;
    uint32_t* AsL = sm + AL_OFF;
    uint32_t* BsH = sm + BH_OFF;
    uint32_t* BsL = sm + BL_OFF;

    const int tid  = threadIdx.x;
    const int lane = tid & 31;
    const int w    = tid >> 5;
    const int mw   = (w >> 2) << 4;        // 0 or 16
    const int nw   = (w & 3) << 4;         // 0,16,32,48
    const int lr   = lane >> 2;            // 0..7
    const int lc   = lane & 3;             // 0..3

    float d[2][4];
#pragma unroll
    for (int g = 0; g < 2; g++)
#pragma unroll
        for (int q = 0; q < 4; q++) d[g][q] = 0.f;

    for (int kc = 0; kc < 4; kc++) {
        __syncthreads();   // prior MMAs done reading smem
        // ---- stage A chunk: 32 rows x 16 float4 ----
#pragma unroll
        for (int i = 0; i < 2; i++) {
            const int idx = tid + (i << 8);
            const int row = idx >> 4, c4 = idx & 15;
            const float4 v = A4[(m0 + row)*64 + (kc << 4) + c4];
            __nv_bfloat162 h01 = __floats2bfloat162_rn(v.x, v.y);
            __nv_bfloat162 h23 = __floats2bfloat162_rn(v.z, v.w);
            float2 f01 = __bfloat1622float2(h01);
            float2 f23 = __bfloat1622float2(h23);
            __nv_bfloat162 l01 = __floats2bfloat162_rn(v.x - f01.x, v.y - f01.y);
            __nv_bfloat162 l23 = __floats2bfloat162_rn(v.z - f23.x, v.w - f23.y);
            const int o = row*36 + c4*2;
            *(uint2*)&AsH[o] = make_uint2(*(uint32_t*)&h01, *(uint32_t*)&h23);
            *(uint2*)&AsL[o] = make_uint2(*(uint32_t*)&l01, *(uint32_t*)&l23);
        }
        // ---- stage B chunk: 64 rows x 16 float4 ----
#pragma unroll
        for (int i = 0; i < 4; i++) {
            const int idx = tid + (i << 8);
            const int row = idx >> 4, c4 = idx & 15;
            const float4 v = B4[(n0 + row)*64 + (kc << 4) + c4];
            __nv_bfloat162 h01 = __floats2bfloat162_rn(v.x, v.y);
            __nv_bfloat162 h23 = __floats2bfloat162_rn(v.z, v.w);
            float2 f01 = __bfloat1622float2(h01);
            float2 f23 = __bfloat1622float2(h23);
            __nv_bfloat162 l01 = __floats2bfloat162_rn(v.x - f01.x, v.y - f01.y);
            __nv_bfloat162 l23 = __floats2bfloat162_rn(v.z - f23.x, v.w - f23.y);
            const int o = row*36 + c4*2;
            *(uint2*)&BsH[o] = make_uint2(*(uint32_t*)&h01, *(uint32_t*)&h23);
            *(uint2*)&BsL[o] = make_uint2(*(uint32_t*)&l01, *(uint32_t*)&l23);
        }
        __syncthreads();

        // ---- mma over 4 k-steps of 16 ----
#pragma unroll
        for (int ks = 0; ks < 4; ks++) {
            const int kpb = ks << 3;
            uint32_t ah[4], al[4];
            const int ab = (mw + lr)*36 + kpb + lc;
            ah[0] = AsH[ab];            al[0] = AsL[ab];
            ah[1] = AsH[ab + 8*36];     al[1] = AsL[ab + 8*36];
            ah[2] = AsH[ab + 4];        al[2] = AsL[ab + 4];
            ah[3] = AsH[ab + 8*36 + 4]; al[3] = AsL[ab + 8*36 + 4];
#pragma unroll
            for (int g = 0; g < 2; g++) {
                const int bb = (nw + g*8 + lr)*36 + kpb + lc;
                uint32_t bh[2], bl[2];
                bh[0] = BsH[bb];     bh[1] = BsH[bb + 4];
                bl[0] = BsL[bb];     bl[1] = BsL[bb + 4];
                mma16816(d[g], ah, bh);
                mma16816(d[g], ah, bl);
                mma16816(d[g], al, bh);
            }
        }
    }

    // ---- epilogue: d[g] frag -> C + bias ----
#pragma unroll
    for (int g = 0; g < 2; g++) {
        const int n = n0 + nw + g*8 + lc*2;
        const float2 bv = *(const float2*)&bias[n];
        const int mA = m0 + mw + lr;
        *(float2*)&C[ mA      *256 + n] = make_float2(d[g][0] + bv.x, d[g][1] + bv.y);
        *(float2*)&C[(mA + 8) *256 + n] = make_float2(d[g][2] + bv.x, d[g][3] + bv.y);
    }
}

// ===========================================================================
// Q/K features. Block = (b, 4 s-rows), 256 threads = 8 warps (warp = head).
// score(i,j) = prod_{w=1..3}( cos(th_w)cos(q_iw) - sin(th_w)sin(q_iw)cos(k_jw) )
// ===========================================================================
__device__ void feat_body(
    const float* __restrict__ x,
    const float* __restrict__ Wq, const float* __restrict__ bq,
    const float* __restrict__ Wk, const float* __restrict__ bk,
    const float* __restrict__ ap, int bid, float* smem)
{
    float (*xs)[256] = (float(*)[256])smem;
    const int b  = bid >> 5;
    const int s0 = (bid & 31) << 2;
    const int tid = threadIdx.x;

    for (int t = tid; t < 1024; t += 256)
        xs[t >> 8][t & 255] = x[(b*Sx + s0 + (t >> 8))*Dx + (t & 255)];
    __syncthreads();

    const int h = tid >> 5, lane = tid & 31;
    float acc[4][8];
#pragma unroll
    for (int s = 0; s < 4; s++)
#pragma unroll
        for (int o = 0; o < 8; o++) acc[s][o] = 0.f;

    const float* wq = Wq + (h*32)*Dx;
    const float* wk = Wk + (h*32)*Dx;

#pragma unroll
    for (int c = 0; c < 8; c++) {
        const int d = lane + (c << 5);
        const float x0 = xs[0][d], x1 = xs[1][d], x2 = xs[2][d], x3 = xs[3][d];
#pragma unroll
        for (int o = 0; o < 4; o++) {
            const float wv = wq[o*Dx + d];
            acc[0][o] = fmaf(x0, wv, acc[0][o]);
            acc[1][o] = fmaf(x1, wv, acc[1][o]);
            acc[2][o] = fmaf(x2, wv, acc[2][o]);
            acc[3][o] = fmaf(x3, wv, acc[3][o]);
        }
#pragma unroll
        for (int o = 0; o < 4; o++) {
            const float wv = wk[o*Dx + d];
            acc[0][4+o] = fmaf(x0, wv, acc[0][4+o]);
            acc[1][4+o] = fmaf(x1, wv, acc[1][4+o]);
            acc[2][4+o] = fmaf(x2, wv, acc[2][4+o]);
            acc[3][4+o] = fmaf(x3, wv, acc[3][4+o]);
        }
    }

#pragma unroll
    for (int s = 0; s < 4; s++)
#pragma unroll
        for (int o = 0; o < 8; o++) {
            float v = acc[s][o];
            v += __shfl_xor_sync(0xffffffffu, v, 16);
            v += __shfl_xor_sync(0xffffffffu, v, 8);
            v += __shfl_xor_sync(0xffffffffu, v, 4);
            v += __shfl_xor_sync(0xffffffffu, v, 2);
            v += __shfl_xor_sync(0xffffffffu, v, 1);
            acc[s][o] = v;
        }

    if (lane < 8) {
        const int sp = lane >> 1;
        const int side = lane & 1;
        const float* bias = side ? bk : bq;
        float vals[4];
#pragma unroll
        for (int wv = 0; wv < 4; wv++)
            vals[wv] = acc[sp][side*4 + wv] + bias[h*32 + wv];

        const float mn = fminf(fminf(vals[0], vals[1]), fminf(vals[2], vals[3]));
        const float mx = fmaxf(fmaxf(vals[0], vals[1]), fmaxf(vals[2], vals[3]));
        const float sc = 3.14159265358979323846f / (mx - mn + 1e-8f);
        const int idx = (b*Hx + h)*Sx + s0 + sp;

        if (side == 0) {
#pragma unroll
            for (int wv = 1; wv < 4; wv++) {
                const float ang = (vals[wv] - mn) * sc;
                float sn, cs;
                sincosf(ang, &sn, &cs);
                const float th = ap[wv];
                g_AB[idx*6 + (wv-1)*2 + 0] = cosf(th) * cs;
                g_AB[idx*6 + (wv-1)*2 + 1] = sinf(th) * sn;
            }
        } else {
            float c1 = cosf((vals[1] - mn) * sc);
            float c2 = cosf((vals[2] - mn) * sc);
            float c3 = cosf((vals[3] - mn) * sc);
            g_CK[idx] = make_float4(c1, c2, c3, 0.f);
        }
    }
}

// ===========================================================================
// Kernel 1: tc V-GEMM (64 blocks) + qk features (128 blocks), 256 thr
// ===========================================================================
__global__ void __launch_bounds__(256) k1_feat_vgemm(
    const float* __restrict__ x,
    const float* __restrict__ Wq, const float* __restrict__ bq,
    const float* __restrict__ Wk, const float* __restrict__ bk,
    const float* __restrict__ ap,
    const float* __restrict__ Wv, const float* __restrict__ bv)
{
    __shared__ __align__(16) uint32_t sm[SM_WORDS];
    const int bx = blockIdx.x;
    if (bx < 64) {
        gemm_tc((const float4*)x, (const float4*)Wv, bv, g_V,
                (bx >> 2) << 5, (bx & 3) << 6, sm);
    } else {
        feat_body(x, Wq, bq, Wk, bk, ap, bx - 64, (float*)sm);
    }
}

// ===========================================================================
// Kernel 2: attention. 128 blocks = (bh, 32-row i-group), 256 threads.
// Scores bounded (|s|<=0.177) -> single-pass softmax, no max subtraction.
// ===========================================================================
__global__ void __launch_bounds__(256) attn_kernel()
{
    const int bx = blockIdx.x;
    const int ig = bx & 3;
    const int bh = bx >> 2;
    const int b = bh >> 3, h = bh & 7;

    __shared__ float4 Vs[1024];      // [j][p]
    __shared__ float4 CKs[128];
    __shared__ float  E[128*33];     // [j][il], pad 33
    __shared__ float  Psum[32*9];
    __shared__ float  Sinv[32];

    const int tid = threadIdx.x;
    const float4* V4 = (const float4*)g_V;
#pragma unroll
    for (int t = 0; t < 4; t++) {
        const int idx = tid + (t << 8);
        const int j = idx >> 3, p = idx & 7;
        Vs[idx] = V4[(b*Sx + j)*64 + h*8 + p];
    }
    if (tid < 128) CKs[tid] = g_CK[bh*Sx + tid];
    __syncthreads();

    const int il = tid & 31;
    const int i  = (ig << 5) + il;

    {
        const int jg = tid >> 5;
        const float* ab = &g_AB[(bh*Sx + i)*6];
        const float A1 = ab[0], B1 = ab[1];
        const float A2 = ab[2], B2 = ab[3];
        const float A3 = ab[4], B3 = ab[5];
        const float SCALE = 0.17677669529663687f;
        float s = 0.f;
#pragma unroll
        for (int jj = 0; jj < 16; jj++) {
            const int j = (jg << 4) + jj;
            const float4 ck = CKs[j];
            const float sc = (A1 - B1*ck.x) * (A2 - B2*ck.y) * (A3 - B3*ck.z);
            const float e = __expf(sc * SCALE);
            E[j*33 + il] = e;
            s += e;
        }
        Psum[il*9 + jg] = s;
    }
    __syncthreads();
    if (tid < 32) {
        float s = 0.f;
#pragma unroll
        for (int jg = 0; jg < 8; jg++) s += Psum[tid*9 + jg];
        Sinv[tid] = 1.0f / s;
    }
    __syncthreads();

    {
        const int p = tid >> 5;
        float4 o = make_float4(0.f, 0.f, 0.f, 0.f);
#pragma unroll 8
        for (int j = 0; j < 128; j++) {
            const float e = E[j*33 + il];
            const float4 v = Vs[(j << 3) + p];
            o.x = fmaf(e, v.x, o.x);
            o.y = fmaf(e, v.y, o.y);
            o.z = fmaf(e, v.z, o.z);
            o.w = fmaf(e, v.w, o.w);
        }
        const float inv = Sinv[il];
        o.x *= inv; o.y *= inv; o.z *= inv; o.w *= inv;
        ((float4*)g_AO)[(b*Sx + i)*64 + h*8 + p] = o;
    }
}

// ===========================================================================
// Kernel 3: out = g_AO @ Wo.T + bo  (64 tc blocks)
// ===========================================================================
__global__ void __launch_bounds__(256) k3_ogemm(
    const float* __restrict__ Wo, const float* __restrict__ bo,
    float* __restrict__ out)
{
    __shared__ __align__(16) uint32_t sm[SM_WORDS];
    const int bx = blockIdx.x;
    gemm_tc((const float4*)g_AO, (const float4*)Wo, bo, out,
            (bx >> 2) << 5, (bx & 3) << 6, sm);
}

// ===========================================================================
extern "C" void kernel_launch(void* const* d_in, const int* in_sizes, int n_in,
                              void* d_out, int out_size)
{
    const float* x  = (const float*)d_in[0];
    const float* Wq = (const float*)d_in[1];
    const float* bq = (const float*)d_in[2];
    const float* Wk = (const float*)d_in[3];
    const float* bk = (const float*)d_in[4];
    const float* Wv = (const float*)d_in[5];
    const float* bv = (const float*)d_in[6];
    const float* Wo = (const float*)d_in[7];
    const float* bo = (const float*)d_in[8];
    const float* ap = (const float*)d_in[9];
    float* out = (float*)d_out;

    k1_feat_vgemm<<<192, 256>>>(x, Wq, bq, Wk, bk, ap, Wv, bv);
    attn_kernel<<<128, 256>>>();
    k3_ogemm<<<64, 256>>>(Wo, bo, out);
}